// round 3
// baseline (speedup 1.0000x reference)
#include <cuda_runtime.h>

#define BB 512
#define TT 512
#define FF 64
#define HH 128
#define GG 512   // 4*H
#define BT (BB*TT)
#define C_OUT 10

typedef unsigned long long u64;

// ---------- packed f32x2 helpers (Blackwell FFMA2 path) ----------
__device__ __forceinline__ u64 pack2(float x, float y) {
    u64 r; asm("mov.b64 %0, {%1,%2};" : "=l"(r) : "f"(x), "f"(y)); return r;
}
__device__ __forceinline__ u64 ffma2(u64 a, u64 b, u64 c) {
    u64 d; asm("fma.rn.f32x2 %0, %1, %2, %3;" : "=l"(d) : "l"(a), "l"(b), "l"(c)); return d;
}
__device__ __forceinline__ u64 fadd2(u64 a, u64 b) {
    u64 d; asm("add.rn.f32x2 %0, %1, %2;" : "=l"(d) : "l"(a), "l"(b)); return d;
}

__device__ __forceinline__ float sigm(float z) {
    return __fdividef(1.f, 1.f + __expf(-z));
}
__device__ __forceinline__ float tanh_f(float z) {
    return 1.f - __fdividef(2.f, __expf(2.f * z) + 1.f);
}

// ---------- scratch (device globals; no allocation allowed) ----------
__device__ __align__(16) float g_xp[(long)BT * GG];   // 512 MB, reused both layers
__device__ __align__(16) float g_h1[(long)BT * HH];   // 128 MB, layer-1 outputs
__device__ __align__(16) float g_last[BB * HH];
__device__ __align__(16) float g_wt4[2][64 * 256 * 4]; // packed W_hh per layer
__device__ __align__(16) float g_bias[2][GG];

// ---------- prep: pack W_hh into (k2, gate-pair) 16B-interleaved layout ----------
// g_wt4[L][(k2*256+gp)*4 + {0,1,2,3}] = {W[2gp][2k2], W[2gp+1][2k2], W[2gp][2k2+1], W[2gp+1][2k2+1]}
__global__ void prep_kernel(const float* __restrict__ w1hh, const float* __restrict__ w2hh,
                            const float* __restrict__ b1i, const float* __restrict__ b1h,
                            const float* __restrict__ b2i, const float* __restrict__ b2h) {
    int layer = blockIdx.y;
    const float* w = layer ? w2hh : w1hh;
    int gid = blockIdx.x * blockDim.x + threadIdx.x;  // [0, 16384)
    int k2 = gid >> 8;
    int gp = gid & 255;
    int k = 2 * k2;
    float* o = &g_wt4[layer][(size_t)gid * 4];
    o[0] = w[(2 * gp) * HH + k];
    o[1] = w[(2 * gp + 1) * HH + k];
    o[2] = w[(2 * gp) * HH + k + 1];
    o[3] = w[(2 * gp + 1) * HH + k + 1];
    if (gid < GG) {
        g_bias[layer][gid] = layer ? (b2i[gid] + b2h[gid]) : (b1i[gid] + b1h[gid]);
    }
}

// ---------- x-projection GEMM: out[BT][512] = in[BT][K] @ wih[512][K]^T + bias ----------
// Tile: M=32, N=128, full-K in 64-chunks. 256 threads, FFMA2 packed over n-pairs.
__global__ void __launch_bounds__(256) gemm_xproj(
        const float* __restrict__ in_, const float* __restrict__ wih,
        const float* __restrict__ bias, float* __restrict__ out, int K) {
    __shared__ __align__(16) float A_s[64][36];  // +4 pad: 16B-aligned rows, conflict-light
    __shared__ __align__(16) u64   B_s[64][64];  // (w[2n2][k], w[2n2+1][k])

    int tid = threadIdx.x;
    int tc = tid & 31;           // n2 columns {tc, tc+32}
    int tr = tid >> 5;           // row group: m = tr*4 + i
    long m0 = (long)blockIdx.x * 32;
    int n0 = blockIdx.y * 128;

    u64 acc[4][2];
#pragma unroll
    for (int i = 0; i < 4; i++) { acc[i][0] = 0ull; acc[i][1] = 0ull; }

    int ntiles = K >> 6;
    for (int kt = 0; kt < ntiles; kt++) {
        int kbase = kt * 64;
        // A tile: 32 rows x 64 k (coalesced over k)
#pragma unroll
        for (int i = 0; i < 8; i++) {
            int idx = tid + i * 256;     // [0, 2048)
            int m = idx >> 6;
            int kk = idx & 63;
            A_s[kk][m] = in_[(m0 + m) * K + kbase + kk];
        }
        // B tile: 64 k x 64 n-pairs
#pragma unroll
        for (int i = 0; i < 16; i++) {
            int idx = tid + i * 256;     // [0, 4096)
            int kk = idx >> 6;
            int n2 = idx & 63;
            int g = n0 + 2 * n2;
            B_s[kk][n2] = pack2(wih[(long)g * K + kbase + kk],
                                wih[(long)(g + 1) * K + kbase + kk]);
        }
        __syncthreads();
#pragma unroll 8
        for (int kk = 0; kk < 64; kk++) {
            float4 a4 = *(const float4*)&A_s[kk][tr * 4];   // warp-broadcast
            u64 b0 = B_s[kk][tc];
            u64 b1 = B_s[kk][tc + 32];
            u64 aa;
            aa = pack2(a4.x, a4.x); acc[0][0] = ffma2(aa, b0, acc[0][0]); acc[0][1] = ffma2(aa, b1, acc[0][1]);
            aa = pack2(a4.y, a4.y); acc[1][0] = ffma2(aa, b0, acc[1][0]); acc[1][1] = ffma2(aa, b1, acc[1][1]);
            aa = pack2(a4.z, a4.z); acc[2][0] = ffma2(aa, b0, acc[2][0]); acc[2][1] = ffma2(aa, b1, acc[2][1]);
            aa = pack2(a4.w, a4.w); acc[3][0] = ffma2(aa, b0, acc[3][0]); acc[3][1] = ffma2(aa, b1, acc[3][1]);
        }
        __syncthreads();
    }
    // epilogue: + bias, packed stores
    const u64* bias64 = (const u64*)bias;
#pragma unroll
    for (int j = 0; j < 2; j++) {
        int n2 = tc + 32 * j;
        u64 bv = bias64[(n0 >> 1) + n2];
#pragma unroll
        for (int i = 0; i < 4; i++) {
            long row = m0 + tr * 4 + i;
            u64* orow = (u64*)(out + row * GG);
            orow[(n0 >> 1) + n2] = fadd2(acc[i][j], bv);
        }
    }
}

// ---------- LSTM recurrence (persistent over T): 1 CTA = 4 batch rows ----------
// Thread t owns gate-pair gp=t (gates 2t, 2t+1) for all 4 rows.
// W read as coalesced LDG.128 (L1-resident across steps); h broadcast from smem
// as duplicated (h,h) pairs so the inner loop is pure FFMA2.
__global__ void __launch_bounds__(256) lstm_rec(
        const float* __restrict__ xp, const float* __restrict__ wt4,
        float* __restrict__ out, int write_all) {
    __shared__ __align__(16) u64   sh_hd[4][HH];      // (h,h) duplicated pairs
    __shared__ __align__(16) float sh_gates[4][GG];

    int tid = threadIdx.x;
    int b0 = blockIdx.x * 4;

    // zero init h
    sh_hd[tid >> 7][tid & 127] = 0ull;
    sh_hd[2 + (tid >> 7)][tid & 127] = 0ull;
    float c_reg[2] = {0.f, 0.f};
    __syncthreads();

    const int gp = tid;  // [0, 256)
    const ulonglong2* wp = (const ulonglong2*)wt4 + gp;

    for (int t = 0; t < TT; t++) {
        // xp loads issued first (independent of h -> latency hidden behind dot loop)
        u64 xpv0 = *(const u64*)(xp + ((long)(b0 + 0) * TT + t) * GG + 2 * gp);
        u64 xpv1 = *(const u64*)(xp + ((long)(b0 + 1) * TT + t) * GG + 2 * gp);
        u64 xpv2 = *(const u64*)(xp + ((long)(b0 + 2) * TT + t) * GG + 2 * gp);
        u64 xpv3 = *(const u64*)(xp + ((long)(b0 + 3) * TT + t) * GG + 2 * gp);

        u64 acc0 = 0ull, acc1 = 0ull, acc2 = 0ull, acc3 = 0ull;
#pragma unroll 4
        for (int k2 = 0; k2 < 64; k2++) {
            ulonglong2 w = wp[(size_t)k2 * 256];   // (pair@k, pair@k+1), coalesced
            ulonglong2 h0 = *(const ulonglong2*)&sh_hd[0][2 * k2];
            acc0 = ffma2(w.x, h0.x, acc0); acc0 = ffma2(w.y, h0.y, acc0);
            ulonglong2 h1 = *(const ulonglong2*)&sh_hd[1][2 * k2];
            acc1 = ffma2(w.x, h1.x, acc1); acc1 = ffma2(w.y, h1.y, acc1);
            ulonglong2 h2 = *(const ulonglong2*)&sh_hd[2][2 * k2];
            acc2 = ffma2(w.x, h2.x, acc2); acc2 = ffma2(w.y, h2.y, acc2);
            ulonglong2 h3 = *(const ulonglong2*)&sh_hd[3][2 * k2];
            acc3 = ffma2(w.x, h3.x, acc3); acc3 = ffma2(w.y, h3.y, acc3);
        }
        acc0 = fadd2(acc0, xpv0);
        acc1 = fadd2(acc1, xpv1);
        acc2 = fadd2(acc2, xpv2);
        acc3 = fadd2(acc3, xpv3);
        ((u64*)sh_gates[0])[gp] = acc0;
        ((u64*)sh_gates[1])[gp] = acc1;
        ((u64*)sh_gates[2])[gp] = acc2;
        ((u64*)sh_gates[3])[gp] = acc3;
        __syncthreads();

        // state update: 512 hidden units / 256 threads = 2 each (fixed mapping -> c in regs)
#pragma unroll
        for (int u = 0; u < 2; u++) {
            int idx = tid + u * 256;
            int b = idx >> 7;
            int j = idx & 127;
            float zi = sh_gates[b][j];
            float zf = sh_gates[b][HH + j];
            float zg = sh_gates[b][2 * HH + j];
            float zo = sh_gates[b][3 * HH + j];
            float iv = sigm(zi);
            float fv = sigm(zf);
            float gv = tanh_f(zg);
            float ov = sigm(zo);
            float c = fv * c_reg[u] + iv * gv;
            c_reg[u] = c;
            float h = ov * tanh_f(c);
            sh_hd[b][j] = pack2(h, h);
            if (write_all) {
                out[((long)(b0 + b) * TT + t) * HH + j] = h;
            } else if (t == TT - 1) {
                out[(b0 + b) * HH + j] = h;
            }
        }
        __syncthreads();
    }
}

// ---------- final FC + sigmoid: out[512][10] ----------
__global__ void fc_kernel(const float* __restrict__ last, const float* __restrict__ wfc,
                          const float* __restrict__ bfc, float* __restrict__ out) {
    int b = blockIdx.x;
    int lane = threadIdx.x;  // 32 threads
    float4 v = ((const float4*)(last + b * HH))[lane];
    for (int c = 0; c < C_OUT; c++) {
        float4 w = ((const float4*)(wfc + c * HH))[lane];
        float s = v.x * w.x + v.y * w.y + v.z * w.z + v.w * w.w;
#pragma unroll
        for (int off = 16; off; off >>= 1) s += __shfl_xor_sync(0xffffffffu, s, off);
        if (lane == 0) out[b * C_OUT + c] = sigm(s + bfc[c]);
    }
}

extern "C" void kernel_launch(void* const* d_in, const int* in_sizes, int n_in,
                              void* d_out, int out_size) {
    const float* x     = (const float*)d_in[0];
    const float* w1_ih = (const float*)d_in[1];
    const float* w1_hh = (const float*)d_in[2];
    const float* b1_ih = (const float*)d_in[3];
    const float* b1_hh = (const float*)d_in[4];
    const float* w2_ih = (const float*)d_in[5];
    const float* w2_hh = (const float*)d_in[6];
    const float* b2_ih = (const float*)d_in[7];
    const float* b2_hh = (const float*)d_in[8];
    const float* w_fc  = (const float*)d_in[9];
    const float* b_fc  = (const float*)d_in[10];
    float* out = (float*)d_out;

    float *xp, *h1, *last, *wt4, *bias;
    cudaGetSymbolAddress((void**)&xp,   g_xp);
    cudaGetSymbolAddress((void**)&h1,   g_h1);
    cudaGetSymbolAddress((void**)&last, g_last);
    cudaGetSymbolAddress((void**)&wt4,  g_wt4);
    cudaGetSymbolAddress((void**)&bias, g_bias);

    const float* wt4_1  = wt4;
    const float* wt4_2  = wt4 + 64 * 256 * 4;
    const float* bias_1 = bias;
    const float* bias_2 = bias + GG;

    prep_kernel<<<dim3(64, 2), 256>>>(w1_hh, w2_hh, b1_ih, b1_hh, b2_ih, b2_hh);

    // Layer 1
    gemm_xproj<<<dim3(BT / 32, 4), 256>>>(x, w1_ih, bias_1, xp, FF);
    lstm_rec<<<BB / 4, 256>>>(xp, wt4_1, h1, 1);

    // Layer 2
    gemm_xproj<<<dim3(BT / 32, 4), 256>>>(h1, w2_ih, bias_2, xp, HH);
    lstm_rec<<<BB / 4, 256>>>(xp, wt4_2, last, 0);

    // FC head
    fc_kernel<<<BB, 32>>>(last, w_fc, b_fc, out);
}

// round 4
// speedup vs baseline: 1.0040x; 1.0040x over previous
#include <cuda_runtime.h>

#define BB 512
#define TT 512
#define FF 64
#define HH 128
#define GG 512   // 4*H
#define BT (BB*TT)
#define C_OUT 10

typedef unsigned long long u64;

// ---------- packed f32x2 helpers (Blackwell FFMA2 path) ----------
__device__ __forceinline__ u64 pack2(float x, float y) {
    u64 r; asm("mov.b64 %0, {%1,%2};" : "=l"(r) : "f"(x), "f"(y)); return r;
}
__device__ __forceinline__ u64 ffma2(u64 a, u64 b, u64 c) {
    u64 d; asm("fma.rn.f32x2 %0, %1, %2, %3;" : "=l"(d) : "l"(a), "l"(b), "l"(c)); return d;
}
__device__ __forceinline__ u64 fadd2(u64 a, u64 b) {
    u64 d; asm("add.rn.f32x2 %0, %1, %2;" : "=l"(d) : "l"(a), "l"(b)); return d;
}

__device__ __forceinline__ float sigm(float z) {
    return __fdividef(1.f, 1.f + __expf(-z));
}
__device__ __forceinline__ float tanh_f(float z) {
    return 1.f - __fdividef(2.f, __expf(2.f * z) + 1.f);
}

// ---------- scratch (device globals; no allocation allowed) ----------
__device__ __align__(16) float g_xp[(long)BT * GG];   // 512 MB, reused both layers
__device__ __align__(16) float g_h1[(long)BT * HH];   // 128 MB, layer-1 outputs
__device__ __align__(16) float g_last[BB * HH];
__device__ __align__(16) float g_wt4[2][64 * 256 * 4]; // packed W_hh per layer
__device__ __align__(16) float g_bias[2][GG];

// ---------- prep: pack W_hh into (k2, gate-pair) 16B-interleaved layout ----------
// g_wt4[L][(k2*256+gp)*4 + {0,1,2,3}] = {W[2gp][2k2], W[2gp+1][2k2], W[2gp][2k2+1], W[2gp+1][2k2+1]}
__global__ void prep_kernel(const float* __restrict__ w1hh, const float* __restrict__ w2hh,
                            const float* __restrict__ b1i, const float* __restrict__ b1h,
                            const float* __restrict__ b2i, const float* __restrict__ b2h) {
    int layer = blockIdx.y;
    const float* w = layer ? w2hh : w1hh;
    int gid = blockIdx.x * blockDim.x + threadIdx.x;  // [0, 16384)
    int k2 = gid >> 8;
    int gp = gid & 255;
    int k = 2 * k2;
    float* o = &g_wt4[layer][(size_t)gid * 4];
    o[0] = w[(2 * gp) * HH + k];
    o[1] = w[(2 * gp + 1) * HH + k];
    o[2] = w[(2 * gp) * HH + k + 1];
    o[3] = w[(2 * gp + 1) * HH + k + 1];
    if (gid < GG) {
        g_bias[layer][gid] = layer ? (b2i[gid] + b2h[gid]) : (b1i[gid] + b1h[gid]);
    }
}

// ---------- x-projection GEMM: out[BT][512] = in[BT][K] @ wih[512][K]^T + bias ----------
// Tile: M=32, N=128, full-K in 64-chunks. 256 threads, FFMA2 packed over n-pairs.
__global__ void __launch_bounds__(256) gemm_xproj(
        const float* __restrict__ in_, const float* __restrict__ wih,
        const float* __restrict__ bias, float* __restrict__ out, int K) {
    __shared__ __align__(16) float A_s[64][36];  // +4 pad: 16B-aligned rows, conflict-light
    __shared__ __align__(16) u64   B_s[64][64];  // (w[2n2][k], w[2n2+1][k])

    int tid = threadIdx.x;
    int tc = tid & 31;           // n2 columns {tc, tc+32}
    int tr = tid >> 5;           // row group: m = tr*4 + i
    long m0 = (long)blockIdx.x * 32;
    int n0 = blockIdx.y * 128;

    u64 acc[4][2];
#pragma unroll
    for (int i = 0; i < 4; i++) { acc[i][0] = 0ull; acc[i][1] = 0ull; }

    int ntiles = K >> 6;
    for (int kt = 0; kt < ntiles; kt++) {
        int kbase = kt * 64;
        // A tile: 32 rows x 64 k (coalesced over k)
#pragma unroll
        for (int i = 0; i < 8; i++) {
            int idx = tid + i * 256;     // [0, 2048)
            int m = idx >> 6;
            int kk = idx & 63;
            A_s[kk][m] = in_[(m0 + m) * K + kbase + kk];
        }
        // B tile: 64 k x 64 n-pairs
#pragma unroll
        for (int i = 0; i < 16; i++) {
            int idx = tid + i * 256;     // [0, 4096)
            int kk = idx >> 6;
            int n2 = idx & 63;
            int g = n0 + 2 * n2;
            B_s[kk][n2] = pack2(wih[(long)g * K + kbase + kk],
                                wih[(long)(g + 1) * K + kbase + kk]);
        }
        __syncthreads();
#pragma unroll 8
        for (int kk = 0; kk < 64; kk++) {
            float4 a4 = *(const float4*)&A_s[kk][tr * 4];   // warp-broadcast
            u64 b0 = B_s[kk][tc];
            u64 b1 = B_s[kk][tc + 32];
            u64 aa;
            aa = pack2(a4.x, a4.x); acc[0][0] = ffma2(aa, b0, acc[0][0]); acc[0][1] = ffma2(aa, b1, acc[0][1]);
            aa = pack2(a4.y, a4.y); acc[1][0] = ffma2(aa, b0, acc[1][0]); acc[1][1] = ffma2(aa, b1, acc[1][1]);
            aa = pack2(a4.z, a4.z); acc[2][0] = ffma2(aa, b0, acc[2][0]); acc[2][1] = ffma2(aa, b1, acc[2][1]);
            aa = pack2(a4.w, a4.w); acc[3][0] = ffma2(aa, b0, acc[3][0]); acc[3][1] = ffma2(aa, b1, acc[3][1]);
        }
        __syncthreads();
    }
    // epilogue: + bias, packed stores
    const u64* bias64 = (const u64*)bias;
#pragma unroll
    for (int j = 0; j < 2; j++) {
        int n2 = tc + 32 * j;
        u64 bv = bias64[(n0 >> 1) + n2];
#pragma unroll
        for (int i = 0; i < 4; i++) {
            long row = m0 + tr * 4 + i;
            u64* orow = (u64*)(out + row * GG);
            orow[(n0 >> 1) + n2] = fadd2(acc[i][j], bv);
        }
    }
}

// ---------- LSTM recurrence (persistent over T): 1 CTA = 4 batch rows ----------
// Thread t owns gate-pair gp=t (gates 2t, 2t+1) for all 4 rows.
// W read as coalesced LDG.128 (L1-resident across steps); h broadcast from smem
// as duplicated (h,h) pairs so the inner loop is pure FFMA2.
__global__ void __launch_bounds__(256) lstm_rec(
        const float* __restrict__ xp, const float* __restrict__ wt4,
        float* __restrict__ out, int write_all) {
    __shared__ __align__(16) u64   sh_hd[4][HH];      // (h,h) duplicated pairs
    __shared__ __align__(16) float sh_gates[4][GG];

    int tid = threadIdx.x;
    int b0 = blockIdx.x * 4;

    // zero init h
    sh_hd[tid >> 7][tid & 127] = 0ull;
    sh_hd[2 + (tid >> 7)][tid & 127] = 0ull;
    float c_reg[2] = {0.f, 0.f};
    __syncthreads();

    const int gp = tid;  // [0, 256)
    const ulonglong2* wp = (const ulonglong2*)wt4 + gp;

    for (int t = 0; t < TT; t++) {
        // xp loads issued first (independent of h -> latency hidden behind dot loop)
        u64 xpv0 = *(const u64*)(xp + ((long)(b0 + 0) * TT + t) * GG + 2 * gp);
        u64 xpv1 = *(const u64*)(xp + ((long)(b0 + 1) * TT + t) * GG + 2 * gp);
        u64 xpv2 = *(const u64*)(xp + ((long)(b0 + 2) * TT + t) * GG + 2 * gp);
        u64 xpv3 = *(const u64*)(xp + ((long)(b0 + 3) * TT + t) * GG + 2 * gp);

        u64 acc0 = 0ull, acc1 = 0ull, acc2 = 0ull, acc3 = 0ull;
#pragma unroll 4
        for (int k2 = 0; k2 < 64; k2++) {
            ulonglong2 w = wp[(size_t)k2 * 256];   // (pair@k, pair@k+1), coalesced
            ulonglong2 h0 = *(const ulonglong2*)&sh_hd[0][2 * k2];
            acc0 = ffma2(w.x, h0.x, acc0); acc0 = ffma2(w.y, h0.y, acc0);
            ulonglong2 h1 = *(const ulonglong2*)&sh_hd[1][2 * k2];
            acc1 = ffma2(w.x, h1.x, acc1); acc1 = ffma2(w.y, h1.y, acc1);
            ulonglong2 h2 = *(const ulonglong2*)&sh_hd[2][2 * k2];
            acc2 = ffma2(w.x, h2.x, acc2); acc2 = ffma2(w.y, h2.y, acc2);
            ulonglong2 h3 = *(const ulonglong2*)&sh_hd[3][2 * k2];
            acc3 = ffma2(w.x, h3.x, acc3); acc3 = ffma2(w.y, h3.y, acc3);
        }
        acc0 = fadd2(acc0, xpv0);
        acc1 = fadd2(acc1, xpv1);
        acc2 = fadd2(acc2, xpv2);
        acc3 = fadd2(acc3, xpv3);
        ((u64*)sh_gates[0])[gp] = acc0;
        ((u64*)sh_gates[1])[gp] = acc1;
        ((u64*)sh_gates[2])[gp] = acc2;
        ((u64*)sh_gates[3])[gp] = acc3;
        __syncthreads();

        // state update: 512 hidden units / 256 threads = 2 each (fixed mapping -> c in regs)
#pragma unroll
        for (int u = 0; u < 2; u++) {
            int idx = tid + u * 256;
            int b = idx >> 7;
            int j = idx & 127;
            float zi = sh_gates[b][j];
            float zf = sh_gates[b][HH + j];
            float zg = sh_gates[b][2 * HH + j];
            float zo = sh_gates[b][3 * HH + j];
            float iv = sigm(zi);
            float fv = sigm(zf);
            float gv = tanh_f(zg);
            float ov = sigm(zo);
            float c = fv * c_reg[u] + iv * gv;
            c_reg[u] = c;
            float h = ov * tanh_f(c);
            sh_hd[b][j] = pack2(h, h);
            if (write_all) {
                out[((long)(b0 + b) * TT + t) * HH + j] = h;
            } else if (t == TT - 1) {
                out[(b0 + b) * HH + j] = h;
            }
        }
        __syncthreads();
    }
}

// ---------- final FC + sigmoid: out[512][10] ----------
__global__ void fc_kernel(const float* __restrict__ last, const float* __restrict__ wfc,
                          const float* __restrict__ bfc, float* __restrict__ out) {
    int b = blockIdx.x;
    int lane = threadIdx.x;  // 32 threads
    float4 v = ((const float4*)(last + b * HH))[lane];
    for (int c = 0; c < C_OUT; c++) {
        float4 w = ((const float4*)(wfc + c * HH))[lane];
        float s = v.x * w.x + v.y * w.y + v.z * w.z + v.w * w.w;
#pragma unroll
        for (int off = 16; off; off >>= 1) s += __shfl_xor_sync(0xffffffffu, s, off);
        if (lane == 0) out[b * C_OUT + c] = sigm(s + bfc[c]);
    }
}

extern "C" void kernel_launch(void* const* d_in, const int* in_sizes, int n_in,
                              void* d_out, int out_size) {
    const float* x     = (const float*)d_in[0];
    const float* w1_ih = (const float*)d_in[1];
    const float* w1_hh = (const float*)d_in[2];
    const float* b1_ih = (const float*)d_in[3];
    const float* b1_hh = (const float*)d_in[4];
    const float* w2_ih = (const float*)d_in[5];
    const float* w2_hh = (const float*)d_in[6];
    const float* b2_ih = (const float*)d_in[7];
    const float* b2_hh = (const float*)d_in[8];
    const float* w_fc  = (const float*)d_in[9];
    const float* b_fc  = (const float*)d_in[10];
    float* out = (float*)d_out;

    float *xp, *h1, *last, *wt4, *bias;
    cudaGetSymbolAddress((void**)&xp,   g_xp);
    cudaGetSymbolAddress((void**)&h1,   g_h1);
    cudaGetSymbolAddress((void**)&last, g_last);
    cudaGetSymbolAddress((void**)&wt4,  g_wt4);
    cudaGetSymbolAddress((void**)&bias, g_bias);

    const float* wt4_1  = wt4;
    const float* wt4_2  = wt4 + 64 * 256 * 4;
    const float* bias_1 = bias;
    const float* bias_2 = bias + GG;

    prep_kernel<<<dim3(64, 2), 256>>>(w1_hh, w2_hh, b1_ih, b1_hh, b2_ih, b2_hh);

    // Layer 1
    gemm_xproj<<<dim3(BT / 32, 4), 256>>>(x, w1_ih, bias_1, xp, FF);
    lstm_rec<<<BB / 4, 256>>>(xp, wt4_1, h1, 1);

    // Layer 2
    gemm_xproj<<<dim3(BT / 32, 4), 256>>>(h1, w2_ih, bias_2, xp, HH);
    lstm_rec<<<BB / 4, 256>>>(xp, wt4_2, last, 0);

    // FC head
    fc_kernel<<<BB, 32>>>(last, w_fc, b_fc, out);
}

// round 6
// speedup vs baseline: 2.2123x; 2.2035x over previous
#include <cuda_runtime.h>

#define BB 512
#define TT 512
#define FF 64
#define HH 128
#define GG 512   // 4*H
#define BT (BB*TT)
#define C_OUT 10

typedef unsigned long long u64;

// ---------- packed f32x2 helpers (Blackwell FFMA2 path) ----------
__device__ __forceinline__ u64 pack2(float x, float y) {
    u64 r; asm("mov.b64 %0, {%1,%2};" : "=l"(r) : "f"(x), "f"(y)); return r;
}
__device__ __forceinline__ u64 ffma2(u64 a, u64 b, u64 c) {
    u64 d; asm("fma.rn.f32x2 %0, %1, %2, %3;" : "=l"(d) : "l"(a), "l"(b), "l"(c)); return d;
}
__device__ __forceinline__ u64 fadd2(u64 a, u64 b) {
    u64 d; asm("add.rn.f32x2 %0, %1, %2;" : "=l"(d) : "l"(a), "l"(b)); return d;
}

__device__ __forceinline__ float sigm(float z) {
    return __fdividef(1.f, 1.f + __expf(-z));
}
__device__ __forceinline__ float tanh_f(float z) {
    return 1.f - __fdividef(2.f, __expf(2.f * z) + 1.f);
}

// ---------- scratch (device globals; no allocation allowed) ----------
__device__ __align__(16) float g_xp[(long)BT * GG];   // 512 MB, reused both layers
__device__ __align__(16) float g_h1[(long)BT * HH];   // 128 MB, layer-1 outputs
__device__ __align__(16) float g_last[BB * HH];
__device__ __align__(16) float g_wt4[2][64 * 256 * 4]; // packed W_hh per layer
__device__ __align__(16) float g_bias[2][GG];

// ---------- prep: pack W_hh into (k2, gate-pair) 16B-interleaved layout ----------
// g_wt4[L][(k2*256+gp)*4 + {0,1,2,3}] = {W[2gp][2k2], W[2gp+1][2k2], W[2gp][2k2+1], W[2gp+1][2k2+1]}
__global__ void prep_kernel(const float* __restrict__ w1hh, const float* __restrict__ w2hh,
                            const float* __restrict__ b1i, const float* __restrict__ b1h,
                            const float* __restrict__ b2i, const float* __restrict__ b2h) {
    int layer = blockIdx.y;
    const float* w = layer ? w2hh : w1hh;
    int gid = blockIdx.x * blockDim.x + threadIdx.x;  // [0, 16384)
    int k2 = gid >> 8;
    int gp = gid & 255;
    int k = 2 * k2;
    float* o = &g_wt4[layer][(size_t)gid * 4];
    o[0] = w[(2 * gp) * HH + k];
    o[1] = w[(2 * gp + 1) * HH + k];
    o[2] = w[(2 * gp) * HH + k + 1];
    o[3] = w[(2 * gp + 1) * HH + k + 1];
    if (gid < GG) {
        g_bias[layer][gid] = layer ? (b2i[gid] + b2h[gid]) : (b1i[gid] + b1h[gid]);
    }
}

// ---------- x-projection GEMM v2: out[BT][512] = in[BT][K] @ wih[512][K]^T + bias ----------
// CTA tile 128m x 128n, BK=32, 256 threads, per-thread 8m x 8n (4 n-pairs).
// Per kk: 4 LDS.128 + 8 dup-movs (alu pipe) + 32 FFMA2 -> FMA-pipe bound.
#define GBM 128
#define GBN 128
#define GBK 32

__global__ void __launch_bounds__(256, 2) gemm_xproj2(
        const float* __restrict__ in_, const float* __restrict__ wih,
        const float* __restrict__ bias, float* __restrict__ out, int K) {
    __shared__ __align__(16) float A_s[GBK][GBM + 4];     // row stride 132 floats
    __shared__ __align__(16) u64   B_s[GBK][GBN / 2 + 2]; // row stride 66 pairs

    int tid = threadIdx.x;
    int tx = tid & 15;        // n-group: pairs {2tx,2tx+1, 32+2tx,32+2tx+1}
    int ty = tid >> 4;        // m-group: m in {ty*4..+3, 64+ty*4..+3}
    long m0 = (long)blockIdx.x * GBM;
    int n0 = blockIdx.y * GBN;

    u64 acc[8][4];
#pragma unroll
    for (int i = 0; i < 8; i++)
#pragma unroll
        for (int j = 0; j < 4; j++) acc[i][j] = 0ull;

    // loader indices
    int a_lk = (tid & 7) * 4;      // k offset for A loads (float4)
    int a_lm = tid >> 3;           // m base (0..31), +32*i
    int b_lp = tid >> 2;           // n-pair 0..63
    int b_kq = (tid & 3) * 8;      // k offset, 8 k per thread

    for (int kt = 0; kt < K; kt += GBK) {
        // ---- A tile: 128m x 32k, transposed store A_s[k][m] ----
#pragma unroll
        for (int i = 0; i < 4; i++) {
            int m = a_lm + 32 * i;
            float4 v = *(const float4*)&in_[(m0 + m) * K + kt + a_lk];
            A_s[a_lk + 0][m] = v.x;
            A_s[a_lk + 1][m] = v.y;
            A_s[a_lk + 2][m] = v.z;
            A_s[a_lk + 3][m] = v.w;
        }
        // ---- B tile: 32k x 64 n-pairs, pair-packed ----
        {
            int g = n0 + 2 * b_lp;
            const float* w0 = &wih[(long)g * K + kt + b_kq];
            const float* w1 = &wih[(long)(g + 1) * K + kt + b_kq];
            float4 x0 = *(const float4*)(w0);
            float4 x1 = *(const float4*)(w0 + 4);
            float4 y0 = *(const float4*)(w1);
            float4 y1 = *(const float4*)(w1 + 4);
            B_s[b_kq + 0][b_lp] = pack2(x0.x, y0.x);
            B_s[b_kq + 1][b_lp] = pack2(x0.y, y0.y);
            B_s[b_kq + 2][b_lp] = pack2(x0.z, y0.z);
            B_s[b_kq + 3][b_lp] = pack2(x0.w, y0.w);
            B_s[b_kq + 4][b_lp] = pack2(x1.x, y1.x);
            B_s[b_kq + 5][b_lp] = pack2(x1.y, y1.y);
            B_s[b_kq + 6][b_lp] = pack2(x1.z, y1.z);
            B_s[b_kq + 7][b_lp] = pack2(x1.w, y1.w);
        }
        __syncthreads();

#pragma unroll
        for (int kk = 0; kk < GBK; kk++) {
            float4 a0 = *(const float4*)&A_s[kk][ty * 4];
            float4 a1 = *(const float4*)&A_s[kk][64 + ty * 4];
            ulonglong2 bA = *(const ulonglong2*)&B_s[kk][2 * tx];
            ulonglong2 bB = *(const ulonglong2*)&B_s[kk][32 + 2 * tx];
            u64 ad;
#define GEMM_ROW(r, av) \
            ad = pack2(av, av); \
            acc[r][0] = ffma2(ad, bA.x, acc[r][0]); \
            acc[r][1] = ffma2(ad, bA.y, acc[r][1]); \
            acc[r][2] = ffma2(ad, bB.x, acc[r][2]); \
            acc[r][3] = ffma2(ad, bB.y, acc[r][3]);
            GEMM_ROW(0, a0.x)
            GEMM_ROW(1, a0.y)
            GEMM_ROW(2, a0.z)
            GEMM_ROW(3, a0.w)
            GEMM_ROW(4, a1.x)
            GEMM_ROW(5, a1.y)
            GEMM_ROW(6, a1.z)
            GEMM_ROW(7, a1.w)
#undef GEMM_ROW
        }
        __syncthreads();
    }

    // ---- epilogue: + bias, packed 16B stores ----
    const u64* bias64 = (const u64*)bias;
    u64 bv0 = bias64[n0 / 2 + 2 * tx];
    u64 bv1 = bias64[n0 / 2 + 2 * tx + 1];
    u64 bv2 = bias64[n0 / 2 + 32 + 2 * tx];
    u64 bv3 = bias64[n0 / 2 + 32 + 2 * tx + 1];
#pragma unroll
    for (int r = 0; r < 8; r++) {
        int m = (r < 4) ? (ty * 4 + r) : (64 + ty * 4 + (r - 4));
        u64* orow = (u64*)(out + (m0 + m) * GG);
        ulonglong2 s0, s1;
        s0.x = fadd2(acc[r][0], bv0); s0.y = fadd2(acc[r][1], bv1);
        s1.x = fadd2(acc[r][2], bv2); s1.y = fadd2(acc[r][3], bv3);
        *(ulonglong2*)&orow[n0 / 2 + 2 * tx] = s0;
        *(ulonglong2*)&orow[n0 / 2 + 32 + 2 * tx] = s1;
    }
}

// ---------- LSTM recurrence v2: W_hh fully on-chip (half regs, half smem) ----------
// 1 CTA = 4 batch rows, 256 threads, thread t owns gate-pair gp=t.
// k in [0,64): W in registers (wreg[64] u64, fully unrolled).
// k in [64,128): W in smem (128KB), coalesced conflict-free ulonglong2 reads.
// h duplicated (h,h) pairs in smem, broadcast reads.
#define LSTM_SMEM_BYTES (131072 + 4096 + 8192)

__global__ void __launch_bounds__(256, 1) lstm_rec2(
        const float* __restrict__ xp, const float* __restrict__ wt4,
        float* __restrict__ out, int write_all) {
    extern __shared__ __align__(16) char smem_raw[];
    ulonglong2* wsm = (ulonglong2*)smem_raw;                       // [32][256] -> 128KB
    u64 (*hd)[HH]   = (u64(*)[HH])(smem_raw + 131072);             // [4][128] dup pairs, 4KB
    float (*sg)[GG] = (float(*)[GG])(smem_raw + 131072 + 4096);    // [4][512] gates, 8KB

    int tid = threadIdx.x;
    int b0 = blockIdx.x * 4;
    const int gp = tid;

    const ulonglong2* wp = (const ulonglong2*)wt4 + gp;

    // W register half: k2 in [0,32)  (k in [0,64))
    u64 wreg[64];
#pragma unroll
    for (int k2 = 0; k2 < 32; k2++) {
        ulonglong2 w = wp[(size_t)k2 * 256];
        wreg[2 * k2]     = w.x;
        wreg[2 * k2 + 1] = w.y;
    }
    // W smem half: k2 in [32,64) -> wsm[k2-32][gp]
    for (int k2 = 0; k2 < 32; k2++) {
        wsm[k2 * 256 + gp] = wp[(size_t)(32 + k2) * 256];
    }

    // init h = 0
    hd[(tid >> 7)][tid & 127] = 0ull;
    hd[2 + (tid >> 7)][tid & 127] = 0ull;
    float c_reg[2] = {0.f, 0.f};
    __syncthreads();

    for (int t = 0; t < TT; t++) {
        // xp loads first (independent of h)
        u64 xpv0 = *(const u64*)(xp + ((long)(b0 + 0) * TT + t) * GG + 2 * gp);
        u64 xpv1 = *(const u64*)(xp + ((long)(b0 + 1) * TT + t) * GG + 2 * gp);
        u64 xpv2 = *(const u64*)(xp + ((long)(b0 + 2) * TT + t) * GG + 2 * gp);
        u64 xpv3 = *(const u64*)(xp + ((long)(b0 + 3) * TT + t) * GG + 2 * gp);

        u64 acc0 = 0ull, acc1 = 0ull, acc2 = 0ull, acc3 = 0ull;

        // ---- register half: k in [0,64) ----
#pragma unroll
        for (int k2 = 0; k2 < 32; k2++) {
            ulonglong2 h0 = *(const ulonglong2*)&hd[0][2 * k2];
            ulonglong2 h1 = *(const ulonglong2*)&hd[1][2 * k2];
            ulonglong2 h2 = *(const ulonglong2*)&hd[2][2 * k2];
            ulonglong2 h3 = *(const ulonglong2*)&hd[3][2 * k2];
            acc0 = ffma2(wreg[2 * k2], h0.x, acc0); acc0 = ffma2(wreg[2 * k2 + 1], h0.y, acc0);
            acc1 = ffma2(wreg[2 * k2], h1.x, acc1); acc1 = ffma2(wreg[2 * k2 + 1], h1.y, acc1);
            acc2 = ffma2(wreg[2 * k2], h2.x, acc2); acc2 = ffma2(wreg[2 * k2 + 1], h2.y, acc2);
            acc3 = ffma2(wreg[2 * k2], h3.x, acc3); acc3 = ffma2(wreg[2 * k2 + 1], h3.y, acc3);
        }
        // ---- smem half: k in [64,128) ----
#pragma unroll
        for (int k2 = 0; k2 < 32; k2++) {
            ulonglong2 w = wsm[k2 * 256 + gp];
            ulonglong2 h0 = *(const ulonglong2*)&hd[0][64 + 2 * k2];
            ulonglong2 h1 = *(const ulonglong2*)&hd[1][64 + 2 * k2];
            ulonglong2 h2 = *(const ulonglong2*)&hd[2][64 + 2 * k2];
            ulonglong2 h3 = *(const ulonglong2*)&hd[3][64 + 2 * k2];
            acc0 = ffma2(w.x, h0.x, acc0); acc0 = ffma2(w.y, h0.y, acc0);
            acc1 = ffma2(w.x, h1.x, acc1); acc1 = ffma2(w.y, h1.y, acc1);
            acc2 = ffma2(w.x, h2.x, acc2); acc2 = ffma2(w.y, h2.y, acc2);
            acc3 = ffma2(w.x, h3.x, acc3); acc3 = ffma2(w.y, h3.y, acc3);
        }

        acc0 = fadd2(acc0, xpv0);
        acc1 = fadd2(acc1, xpv1);
        acc2 = fadd2(acc2, xpv2);
        acc3 = fadd2(acc3, xpv3);
        ((u64*)sg[0])[gp] = acc0;
        ((u64*)sg[1])[gp] = acc1;
        ((u64*)sg[2])[gp] = acc2;
        ((u64*)sg[3])[gp] = acc3;
        __syncthreads();

        // state update: 512 hidden units / 256 threads = 2 each (c in regs)
#pragma unroll
        for (int u = 0; u < 2; u++) {
            int idx = tid + u * 256;
            int b = idx >> 7;
            int j = idx & 127;
            float zi = sg[b][j];
            float zf = sg[b][HH + j];
            float zg = sg[b][2 * HH + j];
            float zo = sg[b][3 * HH + j];
            float iv = sigm(zi);
            float fv = sigm(zf);
            float gv = tanh_f(zg);
            float ov = sigm(zo);
            float c = fv * c_reg[u] + iv * gv;
            c_reg[u] = c;
            float h = ov * tanh_f(c);
            hd[b][j] = pack2(h, h);
            if (write_all) {
                out[((long)(b0 + b) * TT + t) * HH + j] = h;
            } else if (t == TT - 1) {
                out[(b0 + b) * HH + j] = h;
            }
        }
        __syncthreads();
    }
}

// ---------- final FC + sigmoid: out[512][10] ----------
__global__ void fc_kernel(const float* __restrict__ last, const float* __restrict__ wfc,
                          const float* __restrict__ bfc, float* __restrict__ out) {
    int b = blockIdx.x;
    int lane = threadIdx.x;  // 32 threads
    float4 v = ((const float4*)(last + b * HH))[lane];
    for (int c = 0; c < C_OUT; c++) {
        float4 w = ((const float4*)(wfc + c * HH))[lane];
        float s = v.x * w.x + v.y * w.y + v.z * w.z + v.w * w.w;
#pragma unroll
        for (int off = 16; off; off >>= 1) s += __shfl_xor_sync(0xffffffffu, s, off);
        if (lane == 0) out[b * C_OUT + c] = sigm(s + bfc[c]);
    }
}

extern "C" void kernel_launch(void* const* d_in, const int* in_sizes, int n_in,
                              void* d_out, int out_size) {
    const float* x     = (const float*)d_in[0];
    const float* w1_ih = (const float*)d_in[1];
    const float* w1_hh = (const float*)d_in[2];
    const float* b1_ih = (const float*)d_in[3];
    const float* b1_hh = (const float*)d_in[4];
    const float* w2_ih = (const float*)d_in[5];
    const float* w2_hh = (const float*)d_in[6];
    const float* b2_ih = (const float*)d_in[7];
    const float* b2_hh = (const float*)d_in[8];
    const float* w_fc  = (const float*)d_in[9];
    const float* b_fc  = (const float*)d_in[10];
    float* out = (float*)d_out;

    float *xp, *h1, *last, *wt4, *bias;
    cudaGetSymbolAddress((void**)&xp,   g_xp);
    cudaGetSymbolAddress((void**)&h1,   g_h1);
    cudaGetSymbolAddress((void**)&last, g_last);
    cudaGetSymbolAddress((void**)&wt4,  g_wt4);
    cudaGetSymbolAddress((void**)&bias, g_bias);

    const float* wt4_1  = wt4;
    const float* wt4_2  = wt4 + 64 * 256 * 4;
    const float* bias_1 = bias;
    const float* bias_2 = bias + GG;

    cudaFuncSetAttribute(lstm_rec2, cudaFuncAttributeMaxDynamicSharedMemorySize,
                         LSTM_SMEM_BYTES);

    prep_kernel<<<dim3(64, 2), 256>>>(w1_hh, w2_hh, b1_ih, b1_hh, b2_ih, b2_hh);

    // Layer 1
    gemm_xproj2<<<dim3(BT / GBM, GG / GBN), 256>>>(x, w1_ih, bias_1, xp, FF);
    lstm_rec2<<<BB / 4, 256, LSTM_SMEM_BYTES>>>(xp, wt4_1, h1, 1);

    // Layer 2
    gemm_xproj2<<<dim3(BT / GBM, GG / GBN), 256>>>(h1, w2_ih, bias_2, xp, HH);
    lstm_rec2<<<BB / 4, 256, LSTM_SMEM_BYTES>>>(xp, wt4_2, last, 0);

    // FC head
    fc_kernel<<<BB, 32>>>(last, w_fc, b_fc, out);
}

// round 7
// speedup vs baseline: 2.9214x; 1.3205x over previous
#include <cuda_runtime.h>

#define BB 512
#define TT 512
#define FF 64
#define HH 128
#define GG 512   // 4*H
#define BT (BB*TT)
#define C_OUT 10

typedef unsigned long long u64;

// ---------- packed f32x2 helpers (Blackwell FFMA2 path) ----------
__device__ __forceinline__ u64 pack2(float x, float y) {
    u64 r; asm("mov.b64 %0, {%1,%2};" : "=l"(r) : "f"(x), "f"(y)); return r;
}
__device__ __forceinline__ u64 ffma2(u64 a, u64 b, u64 c) {
    u64 d; asm("fma.rn.f32x2 %0, %1, %2, %3;" : "=l"(d) : "l"(a), "l"(b), "l"(c)); return d;
}
__device__ __forceinline__ u64 fadd2(u64 a, u64 b) {
    u64 d; asm("add.rn.f32x2 %0, %1, %2;" : "=l"(d) : "l"(a), "l"(b)); return d;
}
__device__ __forceinline__ float hadd2(u64 a) {
    float lo, hi; asm("mov.b64 {%0,%1}, %2;" : "=f"(lo), "=f"(hi) : "l"(a));
    return lo + hi;
}
__device__ __forceinline__ float lo2(u64 a) {
    float lo, hi; asm("mov.b64 {%0,%1}, %2;" : "=f"(lo), "=f"(hi) : "l"(a));
    return lo;
}
__device__ __forceinline__ float hi2(u64 a) {
    float lo, hi; asm("mov.b64 {%0,%1}, %2;" : "=f"(lo), "=f"(hi) : "l"(a));
    return hi;
}

__device__ __forceinline__ float sigm(float z) {
    return __fdividef(1.f, 1.f + __expf(-z));
}
__device__ __forceinline__ float tanh_f(float z) {
    return 1.f - __fdividef(2.f, __expf(2.f * z) + 1.f);
}

// ---------- scratch (device globals; no allocation allowed) ----------
__device__ __align__(16) float g_xp[(long)BT * GG];   // 512 MB, reused both layers
__device__ __align__(16) float g_h1[(long)BT * HH];   // 128 MB, layer-1 outputs
__device__ __align__(16) float g_last[BB * HH];
__device__ __align__(16) float g_wt4[2][64 * 256 * 4]; // packed W_hh per layer
__device__ __align__(16) float g_bias[2][GG];

// ---------- prep: pack W_hh into k-pair interleaved layout ----------
// g_wt4[L][(k2*256+t)*4 + {0,1,2,3}] = {W[2t][2k2], W[2t][2k2+1], W[2t+1][2k2], W[2t+1][2k2+1]}
// i.e. ulonglong2{ .x = k-pair of gate 2t, .y = k-pair of gate 2t+1 } at (k2, t).
__global__ void prep_kernel(const float* __restrict__ w1hh, const float* __restrict__ w2hh,
                            const float* __restrict__ b1i, const float* __restrict__ b1h,
                            const float* __restrict__ b2i, const float* __restrict__ b2h) {
    int layer = blockIdx.y;
    const float* w = layer ? w2hh : w1hh;
    int gid = blockIdx.x * blockDim.x + threadIdx.x;  // [0, 16384)
    int k2 = gid >> 8;
    int gp = gid & 255;
    int k = 2 * k2;
    float* o = &g_wt4[layer][(size_t)gid * 4];
    o[0] = w[(2 * gp) * HH + k];
    o[1] = w[(2 * gp) * HH + k + 1];
    o[2] = w[(2 * gp + 1) * HH + k];
    o[3] = w[(2 * gp + 1) * HH + k + 1];
    if (gid < GG) {
        g_bias[layer][gid] = layer ? (b2i[gid] + b2h[gid]) : (b1i[gid] + b1h[gid]);
    }
}

// ---------- x-projection GEMM v2: out[BT][512] = in[BT][K] @ wih[512][K]^T + bias ----------
#define GBM 128
#define GBN 128
#define GBK 32

__global__ void __launch_bounds__(256, 2) gemm_xproj2(
        const float* __restrict__ in_, const float* __restrict__ wih,
        const float* __restrict__ bias, float* __restrict__ out, int K) {
    __shared__ __align__(16) float A_s[GBK][GBM + 4];     // row stride 132 floats
    __shared__ __align__(16) u64   B_s[GBK][GBN / 2 + 2]; // row stride 66 pairs

    int tid = threadIdx.x;
    int tx = tid & 15;        // n-group: pairs {2tx,2tx+1, 32+2tx,32+2tx+1}
    int ty = tid >> 4;        // m-group: m in {ty*4..+3, 64+ty*4..+3}
    long m0 = (long)blockIdx.x * GBM;
    int n0 = blockIdx.y * GBN;

    u64 acc[8][4];
#pragma unroll
    for (int i = 0; i < 8; i++)
#pragma unroll
        for (int j = 0; j < 4; j++) acc[i][j] = 0ull;

    int a_lk = (tid & 7) * 4;      // k offset for A loads (float4)
    int a_lm = tid >> 3;           // m base (0..31), +32*i
    int b_lp = tid >> 2;           // n-pair 0..63
    int b_kq = (tid & 3) * 8;      // k offset, 8 k per thread

    for (int kt = 0; kt < K; kt += GBK) {
#pragma unroll
        for (int i = 0; i < 4; i++) {
            int m = a_lm + 32 * i;
            float4 v = *(const float4*)&in_[(m0 + m) * K + kt + a_lk];
            A_s[a_lk + 0][m] = v.x;
            A_s[a_lk + 1][m] = v.y;
            A_s[a_lk + 2][m] = v.z;
            A_s[a_lk + 3][m] = v.w;
        }
        {
            int g = n0 + 2 * b_lp;
            const float* w0 = &wih[(long)g * K + kt + b_kq];
            const float* w1 = &wih[(long)(g + 1) * K + kt + b_kq];
            float4 x0 = *(const float4*)(w0);
            float4 x1 = *(const float4*)(w0 + 4);
            float4 y0 = *(const float4*)(w1);
            float4 y1 = *(const float4*)(w1 + 4);
            B_s[b_kq + 0][b_lp] = pack2(x0.x, y0.x);
            B_s[b_kq + 1][b_lp] = pack2(x0.y, y0.y);
            B_s[b_kq + 2][b_lp] = pack2(x0.z, y0.z);
            B_s[b_kq + 3][b_lp] = pack2(x0.w, y0.w);
            B_s[b_kq + 4][b_lp] = pack2(x1.x, y1.x);
            B_s[b_kq + 5][b_lp] = pack2(x1.y, y1.y);
            B_s[b_kq + 6][b_lp] = pack2(x1.z, y1.z);
            B_s[b_kq + 7][b_lp] = pack2(x1.w, y1.w);
        }
        __syncthreads();

#pragma unroll
        for (int kk = 0; kk < GBK; kk++) {
            float4 a0 = *(const float4*)&A_s[kk][ty * 4];
            float4 a1 = *(const float4*)&A_s[kk][64 + ty * 4];
            ulonglong2 bA = *(const ulonglong2*)&B_s[kk][2 * tx];
            ulonglong2 bB = *(const ulonglong2*)&B_s[kk][32 + 2 * tx];
            u64 ad;
#define GEMM_ROW(r, av) \
            ad = pack2(av, av); \
            acc[r][0] = ffma2(ad, bA.x, acc[r][0]); \
            acc[r][1] = ffma2(ad, bA.y, acc[r][1]); \
            acc[r][2] = ffma2(ad, bB.x, acc[r][2]); \
            acc[r][3] = ffma2(ad, bB.y, acc[r][3]);
            GEMM_ROW(0, a0.x)
            GEMM_ROW(1, a0.y)
            GEMM_ROW(2, a0.z)
            GEMM_ROW(3, a0.w)
            GEMM_ROW(4, a1.x)
            GEMM_ROW(5, a1.y)
            GEMM_ROW(6, a1.z)
            GEMM_ROW(7, a1.w)
#undef GEMM_ROW
        }
        __syncthreads();
    }

    const u64* bias64 = (const u64*)bias;
    u64 bv0 = bias64[n0 / 2 + 2 * tx];
    u64 bv1 = bias64[n0 / 2 + 2 * tx + 1];
    u64 bv2 = bias64[n0 / 2 + 32 + 2 * tx];
    u64 bv3 = bias64[n0 / 2 + 32 + 2 * tx + 1];
#pragma unroll
    for (int r = 0; r < 8; r++) {
        int m = (r < 4) ? (ty * 4 + r) : (64 + ty * 4 + (r - 4));
        u64* orow = (u64*)(out + (m0 + m) * GG);
        ulonglong2 s0, s1;
        s0.x = fadd2(acc[r][0], bv0); s0.y = fadd2(acc[r][1], bv1);
        s1.x = fadd2(acc[r][2], bv2); s1.y = fadd2(acc[r][3], bv3);
        *(ulonglong2*)&orow[n0 / 2 + 2 * tx] = s0;
        *(ulonglong2*)&orow[n0 / 2 + 32 + 2 * tx] = s1;
    }
}

// ---------- LSTM recurrence v3: k-pair FFMA2, non-duplicated h ----------
// 1 CTA = 4 batch rows, 256 threads, thread t owns gates (2t, 2t+1).
// Accumulators are f32x2 over (k, k+1): acc[b][g]. h stored as plain floats;
// one 16B broadcast LDS yields 4 k-values = two ready f32x2 operands (no packs).
// W: k in [0,64) in registers (128 regs), k in [64,128) in smem (128 KB).
#define LSTM_SMEM_BYTES (131072 + 2048 + 8192)

__global__ void __launch_bounds__(256, 1) lstm_rec3(
        const float* __restrict__ xp, const float* __restrict__ wt4,
        float* __restrict__ out, int write_all) {
    extern __shared__ __align__(16) char smem_raw[];
    ulonglong2* wsm = (ulonglong2*)smem_raw;                       // [32][256] -> 128KB
    float (*hs)[HH] = (float(*)[HH])(smem_raw + 131072);           // [4][128] floats, 2KB
    float (*sg)[GG] = (float(*)[GG])(smem_raw + 131072 + 2048);    // [4][512] gates, 8KB

    int tid = threadIdx.x;
    int b0 = blockIdx.x * 4;
    const int t = tid;

    const ulonglong2* wp = (const ulonglong2*)wt4 + t;

    // W register half: k2 in [0,32)  (k in [0,64)): wA = gate 2t pair, wB = gate 2t+1 pair
    u64 wA[32], wB[32];
#pragma unroll
    for (int k2 = 0; k2 < 32; k2++) {
        ulonglong2 w = wp[(size_t)k2 * 256];
        wA[k2] = w.x;
        wB[k2] = w.y;
    }
    // W smem half: k2 in [32,64) -> wsm[k2-32][t]
    for (int k2 = 0; k2 < 32; k2++) {
        wsm[k2 * 256 + t] = wp[(size_t)(32 + k2) * 256];
    }

    // init h = 0
    hs[0][tid & 127] = 0.f; hs[1][tid & 127] = 0.f;
    hs[2][tid & 127] = 0.f; hs[3][tid & 127] = 0.f;
    float c_reg[2] = {0.f, 0.f};
    __syncthreads();

    for (int tstep = 0; tstep < TT; tstep++) {
        // xp loads first (independent of h -> hidden behind dot loop)
        u64 xpv0 = *(const u64*)(xp + ((long)(b0 + 0) * TT + tstep) * GG + 2 * t);
        u64 xpv1 = *(const u64*)(xp + ((long)(b0 + 1) * TT + tstep) * GG + 2 * t);
        u64 xpv2 = *(const u64*)(xp + ((long)(b0 + 2) * TT + tstep) * GG + 2 * t);
        u64 xpv3 = *(const u64*)(xp + ((long)(b0 + 3) * TT + tstep) * GG + 2 * t);

        u64 aA0 = 0, aA1 = 0, aA2 = 0, aA3 = 0;   // gate 2t,   batches 0..3
        u64 aB0 = 0, aB1 = 0, aB2 = 0, aB3 = 0;   // gate 2t+1, batches 0..3

        // ---- register half: k in [0,64), 16 chunks of 4 k ----
#pragma unroll
        for (int c = 0; c < 16; c++) {
            ulonglong2 h0 = *(const ulonglong2*)&hs[0][4 * c];
            ulonglong2 h1 = *(const ulonglong2*)&hs[1][4 * c];
            ulonglong2 h2 = *(const ulonglong2*)&hs[2][4 * c];
            ulonglong2 h3 = *(const ulonglong2*)&hs[3][4 * c];
            u64 wa0 = wA[2 * c], wa1 = wA[2 * c + 1];
            u64 wb0 = wB[2 * c], wb1 = wB[2 * c + 1];
            aA0 = ffma2(wa0, h0.x, aA0); aA0 = ffma2(wa1, h0.y, aA0);
            aB0 = ffma2(wb0, h0.x, aB0); aB0 = ffma2(wb1, h0.y, aB0);
            aA1 = ffma2(wa0, h1.x, aA1); aA1 = ffma2(wa1, h1.y, aA1);
            aB1 = ffma2(wb0, h1.x, aB1); aB1 = ffma2(wb1, h1.y, aB1);
            aA2 = ffma2(wa0, h2.x, aA2); aA2 = ffma2(wa1, h2.y, aA2);
            aB2 = ffma2(wb0, h2.x, aB2); aB2 = ffma2(wb1, h2.y, aB2);
            aA3 = ffma2(wa0, h3.x, aA3); aA3 = ffma2(wa1, h3.y, aA3);
            aB3 = ffma2(wb0, h3.x, aB3); aB3 = ffma2(wb1, h3.y, aB3);
        }
        // ---- smem half: k in [64,128), 16 chunks of 4 k ----
#pragma unroll
        for (int c = 0; c < 16; c++) {
            ulonglong2 w0 = wsm[(2 * c) * 256 + t];       // gates pairs @ k2=32+2c
            ulonglong2 w1 = wsm[(2 * c + 1) * 256 + t];   // gates pairs @ k2=32+2c+1
            ulonglong2 h0 = *(const ulonglong2*)&hs[0][64 + 4 * c];
            ulonglong2 h1 = *(const ulonglong2*)&hs[1][64 + 4 * c];
            ulonglong2 h2 = *(const ulonglong2*)&hs[2][64 + 4 * c];
            ulonglong2 h3 = *(const ulonglong2*)&hs[3][64 + 4 * c];
            aA0 = ffma2(w0.x, h0.x, aA0); aA0 = ffma2(w1.x, h0.y, aA0);
            aB0 = ffma2(w0.y, h0.x, aB0); aB0 = ffma2(w1.y, h0.y, aB0);
            aA1 = ffma2(w0.x, h1.x, aA1); aA1 = ffma2(w1.x, h1.y, aA1);
            aB1 = ffma2(w0.y, h1.x, aB1); aB1 = ffma2(w1.y, h1.y, aB1);
            aA2 = ffma2(w0.x, h2.x, aA2); aA2 = ffma2(w1.x, h2.y, aA2);
            aB2 = ffma2(w0.y, h2.x, aB2); aB2 = ffma2(w1.y, h2.y, aB2);
            aA3 = ffma2(w0.x, h3.x, aA3); aA3 = ffma2(w1.x, h3.y, aA3);
            aB3 = ffma2(w0.y, h3.x, aB3); aB3 = ffma2(w1.y, h3.y, aB3);
        }

        // horizontal add (k-even + k-odd partials) + xp, store gate pair as u64
        ((u64*)sg[0])[t] = pack2(hadd2(aA0) + lo2(xpv0), hadd2(aB0) + hi2(xpv0));
        ((u64*)sg[1])[t] = pack2(hadd2(aA1) + lo2(xpv1), hadd2(aB1) + hi2(xpv1));
        ((u64*)sg[2])[t] = pack2(hadd2(aA2) + lo2(xpv2), hadd2(aB2) + hi2(xpv2));
        ((u64*)sg[3])[t] = pack2(hadd2(aA3) + lo2(xpv3), hadd2(aB3) + hi2(xpv3));
        __syncthreads();

        // state update: 512 hidden units / 256 threads = 2 each (c in regs)
#pragma unroll
        for (int u = 0; u < 2; u++) {
            int idx = tid + u * 256;
            int b = idx >> 7;
            int j = idx & 127;
            float zi = sg[b][j];
            float zf = sg[b][HH + j];
            float zg = sg[b][2 * HH + j];
            float zo = sg[b][3 * HH + j];
            float iv = sigm(zi);
            float fv = sigm(zf);
            float gv = tanh_f(zg);
            float ov = sigm(zo);
            float c = fv * c_reg[u] + iv * gv;
            c_reg[u] = c;
            float h = ov * tanh_f(c);
            hs[b][j] = h;
            if (write_all) {
                out[((long)(b0 + b) * TT + tstep) * HH + j] = h;
            } else if (tstep == TT - 1) {
                out[(b0 + b) * HH + j] = h;
            }
        }
        __syncthreads();
    }
}

// ---------- final FC + sigmoid: out[512][10] ----------
__global__ void fc_kernel(const float* __restrict__ last, const float* __restrict__ wfc,
                          const float* __restrict__ bfc, float* __restrict__ out) {
    int b = blockIdx.x;
    int lane = threadIdx.x;  // 32 threads
    float4 v = ((const float4*)(last + b * HH))[lane];
    for (int c = 0; c < C_OUT; c++) {
        float4 w = ((const float4*)(wfc + c * HH))[lane];
        float s = v.x * w.x + v.y * w.y + v.z * w.z + v.w * w.w;
#pragma unroll
        for (int off = 16; off; off >>= 1) s += __shfl_xor_sync(0xffffffffu, s, off);
        if (lane == 0) out[b * C_OUT + c] = sigm(s + bfc[c]);
    }
}

extern "C" void kernel_launch(void* const* d_in, const int* in_sizes, int n_in,
                              void* d_out, int out_size) {
    const float* x     = (const float*)d_in[0];
    const float* w1_ih = (const float*)d_in[1];
    const float* w1_hh = (const float*)d_in[2];
    const float* b1_ih = (const float*)d_in[3];
    const float* b1_hh = (const float*)d_in[4];
    const float* w2_ih = (const float*)d_in[5];
    const float* w2_hh = (const float*)d_in[6];
    const float* b2_ih = (const float*)d_in[7];
    const float* b2_hh = (const float*)d_in[8];
    const float* w_fc  = (const float*)d_in[9];
    const float* b_fc  = (const float*)d_in[10];
    float* out = (float*)d_out;

    float *xp, *h1, *last, *wt4, *bias;
    cudaGetSymbolAddress((void**)&xp,   g_xp);
    cudaGetSymbolAddress((void**)&h1,   g_h1);
    cudaGetSymbolAddress((void**)&last, g_last);
    cudaGetSymbolAddress((void**)&wt4,  g_wt4);
    cudaGetSymbolAddress((void**)&bias, g_bias);

    const float* wt4_1  = wt4;
    const float* wt4_2  = wt4 + 64 * 256 * 4;
    const float* bias_1 = bias;
    const float* bias_2 = bias + GG;

    cudaFuncSetAttribute(lstm_rec3, cudaFuncAttributeMaxDynamicSharedMemorySize,
                         LSTM_SMEM_BYTES);

    prep_kernel<<<dim3(64, 2), 256>>>(w1_hh, w2_hh, b1_ih, b1_hh, b2_ih, b2_hh);

    // Layer 1
    gemm_xproj2<<<dim3(BT / GBM, GG / GBN), 256>>>(x, w1_ih, bias_1, xp, FF);
    lstm_rec3<<<BB / 4, 256, LSTM_SMEM_BYTES>>>(xp, wt4_1, h1, 1);

    // Layer 2
    gemm_xproj2<<<dim3(BT / GBM, GG / GBN), 256>>>(h1, w2_ih, bias_2, xp, HH);
    lstm_rec3<<<BB / 4, 256, LSTM_SMEM_BYTES>>>(xp, wt4_2, last, 0);

    // FC head
    fc_kernel<<<BB, 32>>>(last, w_fc, b_fc, out);
}